// round 15
// baseline (speedup 1.0000x reference)
#include <cuda_runtime.h>
#include <cuda_fp16.h>
#include <cstdint>

#define N_NODES 100000
#define N_EDGES 1600000
#define D_IN    512
#define D_OUT   64

#define SCAN_BLK 1024
#define N_SCAN_BLKS ((N_NODES + SCAN_BLK - 1) / SCAN_BLK)   // 98

#define GGRID   456            // 3 persistent CTAs per SM
#define NTHREADS 256
#define N_UNITS (N_NODES / 16)          // 6250 warp work units (exact)
#define TOTAL_WARPS (GGRID * 8)         // 3648

#define B_SMEM_HALVES (D_IN * D_OUT)    // 32768 halves = 65536 B
#define SMEM_TOTAL (B_SMEM_HALVES * 2)  // 65536 B

// ---------------- scratch -----------------------------------------------------
__device__ __half g_h[N_NODES * D_OUT];      // 12.8 MB fp16
__device__ int   g_deg[N_NODES];
__device__ int   g_rowstart[N_NODES + 1];
__device__ int   g_cursor[N_NODES];
__device__ int   g_bsum[128];
__device__ int2  g_csr[N_EDGES];             // (col, val-as-int)
__device__ int   g_unit_ctr;

// ---------------- helpers -----------------------------------------------------
__device__ __forceinline__ uint32_t smem_u32(const void* p) {
    uint32_t a;
    asm("{ .reg .u64 t; cvta.to.shared.u64 t, %1; cvt.u32.u64 %0, t; }"
        : "=r"(a) : "l"(p));
    return a;
}

__device__ __forceinline__ uint32_t pack_h2(float lo, float hi) {
    __half2 h = __floats2half2_rn(lo, hi);
    return *reinterpret_cast<uint32_t*>(&h);
}

__device__ __forceinline__ void ldsm_x4_t(uint32_t addr, uint32_t r[4]) {
    asm volatile("ldmatrix.sync.aligned.m8n8.x4.trans.shared.b16 {%0,%1,%2,%3}, [%4];"
                 : "=r"(r[0]), "=r"(r[1]), "=r"(r[2]), "=r"(r[3]) : "r"(addr));
}

__device__ __forceinline__ void mma_f16(float c[4], const uint32_t a[4],
                                        uint32_t b0, uint32_t b1) {
    asm volatile(
        "mma.sync.aligned.m16n8k16.row.col.f32.f16.f16.f32 "
        "{%0,%1,%2,%3}, {%4,%5,%6,%7}, {%8,%9}, {%0,%1,%2,%3};"
        : "+f"(c[0]), "+f"(c[1]), "+f"(c[2]), "+f"(c[3])
        : "r"(a[0]), "r"(a[1]), "r"(a[2]), "r"(a[3]), "r"(b0), "r"(b1));
}

// ---------------- GEMM: barrier-free, per-warp queue, depth-2 prefetch --------
__global__ __launch_bounds__(NTHREADS, 3) void k_gemm_tc(const float* __restrict__ X,
                                                         const float* __restrict__ W) {
    extern __shared__ __align__(16) __half Bsm[];  // [512] rows x 128B, XOR-swizzled

    const int tid  = threadIdx.x;
    const int warp = tid >> 5;
    const int lane = tid & 31;
    const int grp  = lane >> 2;
    const int tig  = lane & 3;

    const uint32_t b_base = smem_u32(Bsm);

    // ---- W -> smem fp16, rows k-permuted (perm-inverse), XOR-16B swizzled ----
    for (int i = tid * 8; i < D_IN * D_OUT; i += NTHREADS * 8) {
        const int kk = i >> 6, nn = i & 63;
        const int kl = kk & 15, kh = kk & ~15;
        const int q = kl >> 2, r = kl & 3;
        const int s = (r < 2) ? (2 * q + r) : (8 + 2 * q + (r - 2));
        const int row = kh | s;
        float4 v0 = *(const float4*)&W[i];
        float4 v1 = *(const float4*)&W[i + 4];
        const int u = (nn >> 3) ^ (row & 7);
        *(uint4*)(Bsm + row * 64 + u * 8) =
            make_uint4(pack_h2(v0.x, v0.y), pack_h2(v0.z, v0.w),
                       pack_h2(v1.x, v1.y), pack_h2(v1.z, v1.w));
    }
    __syncthreads();

    const int l15 = lane & 15;
    const int lhi16 = lane >> 4;

    int unit = blockIdx.x * 8 + warp;

    while (unit < N_UNITS) {
        const int r0 = unit * 16 + grp;
        const int r1 = r0 + 8;
        const float* pA0 = X + (size_t)r0 * D_IN + 4 * tig;
        const float* pA1 = X + (size_t)r1 * D_IN + 4 * tig;

        float acc[8][4];
        #pragma unroll
        for (int j = 0; j < 8; j++)
            #pragma unroll
            for (int e = 0; e < 4; e++) acc[j][e] = 0.f;

        float4 v[2][2];
        v[0][0] = *(const float4*)(pA0);
        v[0][1] = *(const float4*)(pA1);
        v[1][0] = *(const float4*)(pA0 + 16);
        v[1][1] = *(const float4*)(pA1 + 16);

        #pragma unroll 4
        for (int kk = 0; kk < 32; kk++) {
            const int sl = kk & 1;
            uint32_t a[4];
            a[0] = pack_h2(v[sl][0].x, v[sl][0].y);
            a[1] = pack_h2(v[sl][1].x, v[sl][1].y);
            a[2] = pack_h2(v[sl][0].z, v[sl][0].w);
            a[3] = pack_h2(v[sl][1].z, v[sl][1].w);

            if (kk + 2 < 32) {   // refill this slot with k-step kk+2
                v[sl][0] = *(const float4*)(pA0 + (kk + 2) * 16);
                v[sl][1] = *(const float4*)(pA1 + (kk + 2) * 16);
            }

            const int brow = kk * 16 + l15;
            const uint32_t brbase = b_base + brow * 128;
            const int bsw = brow & 7;
            uint32_t b[8][2];
            #pragma unroll
            for (int jj = 0; jj < 4; jj++) {
                uint32_t br[4];
                const int u = ((jj << 1) | lhi16) ^ bsw;
                ldsm_x4_t(brbase + (u << 4), br);
                b[2*jj][0]   = br[0];  b[2*jj][1]   = br[1];
                b[2*jj+1][0] = br[2];  b[2*jj+1][1] = br[3];
            }
            #pragma unroll
            for (int j = 0; j < 8; j++)
                mma_f16(acc[j], a, b[j][0], b[j][1]);
        }

        int nxt = 0;
        if (lane == 0) nxt = atomicAdd(&g_unit_ctr, 1);

        #pragma unroll
        for (int j = 0; j < 8; j++) {
            const int col = j * 8 + tig * 2;
            *(uint32_t*)&g_h[(size_t)r0 * D_OUT + col] = pack_h2(acc[j][0], acc[j][1]);
            *(uint32_t*)&g_h[(size_t)r1 * D_OUT + col] = pack_h2(acc[j][2], acc[j][3]);
        }

        unit = __shfl_sync(0xffffffffu, nxt, 0);
    }
}

// ---------------- CSR build ---------------------------------------------------
__global__ void k_zero_deg() {
    int i = blockIdx.x * blockDim.x + threadIdx.x;
    if (i < N_NODES) g_deg[i] = 0;
    if (i == 0) g_unit_ctr = TOTAL_WARPS;
}

__global__ void k_count(const int* __restrict__ rows) {
    int e = (blockIdx.x * blockDim.x + threadIdx.x) * 2;
    if (e + 1 < N_EDGES) {
        int2 r2 = *(const int2*)&rows[e];
        atomicAdd(&g_deg[r2.x], 1);
        atomicAdd(&g_deg[r2.y], 1);
    } else if (e < N_EDGES) {
        atomicAdd(&g_deg[rows[e]], 1);
    }
}

__global__ void k_scan1() {
    __shared__ int wsum[32];
    const int i = blockIdx.x * SCAN_BLK + threadIdx.x;
    const int v = (i < N_NODES) ? g_deg[i] : 0;
    const int lane = threadIdx.x & 31;
    const int w = threadIdx.x >> 5;

    int x = v;
    #pragma unroll
    for (int o = 1; o < 32; o <<= 1) {
        int y = __shfl_up_sync(0xffffffffu, x, o);
        if (lane >= o) x += y;
    }
    if (lane == 31) wsum[w] = x;
    __syncthreads();
    if (w == 0) {
        int s = wsum[lane];
        int t = s;
        #pragma unroll
        for (int o = 1; o < 32; o <<= 1) {
            int y = __shfl_up_sync(0xffffffffu, t, o);
            if (lane >= o) t += y;
        }
        wsum[lane] = t - s;
        if (lane == 31) g_bsum[blockIdx.x] = t;
    }
    __syncthreads();
    const int excl = x - v + wsum[w];
    if (i < N_NODES) g_rowstart[i] = excl;
}

__global__ void k_scan3() {
    __shared__ int s_boff[128];
    __shared__ int wsum[4];
    const int tid = threadIdx.x;
    if (tid < 128) {
        const int lane = tid & 31;
        const int w = tid >> 5;
        const int v = (tid < N_SCAN_BLKS) ? g_bsum[tid] : 0;
        int x = v;
        #pragma unroll
        for (int o = 1; o < 32; o <<= 1) {
            int y = __shfl_up_sync(0xffffffffu, x, o);
            if (lane >= o) x += y;
        }
        if (lane == 31) wsum[w] = x;
    }
    __syncthreads();
    if (tid < 128) {
        const int lane = tid & 31;
        const int w = tid >> 5;
        const int v = (tid < N_SCAN_BLKS) ? g_bsum[tid] : 0;
        int x = v;
        #pragma unroll
        for (int o = 1; o < 32; o <<= 1) {
            int y = __shfl_up_sync(0xffffffffu, x, o);
            if (lane >= o) x += y;
        }
        int woff = 0;
        for (int j = 0; j < w; j++) woff += wsum[j];
        s_boff[tid] = x - v + woff;
    }
    __syncthreads();

    const int i = blockIdx.x * SCAN_BLK + tid;
    if (i < N_NODES) {
        const int val = g_rowstart[i] + s_boff[blockIdx.x];
        g_rowstart[i] = val;
        g_cursor[i] = val;
    }
    if (i == 0) g_rowstart[N_NODES] = N_EDGES;
}

__global__ void k_fill(const float* __restrict__ vals,
                       const int* __restrict__ rows,
                       const int* __restrict__ cols) {
    int e = (blockIdx.x * blockDim.x + threadIdx.x) * 2;
    if (e + 1 < N_EDGES) {
        int2   r2 = *(const int2*)&rows[e];
        int2   c2 = *(const int2*)&cols[e];
        float2 v2 = *(const float2*)&vals[e];
        int p0 = atomicAdd(&g_cursor[r2.x], 1);
        int p1 = atomicAdd(&g_cursor[r2.y], 1);
        g_csr[p0] = make_int2(c2.x, __float_as_int(v2.x));
        g_csr[p1] = make_int2(c2.y, __float_as_int(v2.y));
    } else if (e < N_EDGES) {
        int p = atomicAdd(&g_cursor[rows[e]], 1);
        g_csr[p] = make_int2(cols[e], __float_as_int(vals[e]));
    }
}

// ---------------- SpMM + ReLU: warp per row, 8-wide MLP -----------------------
__global__ void k_spmm(float* __restrict__ out) {
    const int gwarp = (blockIdx.x * blockDim.x + threadIdx.x) >> 5;
    const int lane = threadIdx.x & 31;
    if (gwarp >= N_NODES) return;

    const int s = g_rowstart[gwarp];
    const int e = g_rowstart[gwarp + 1];

    const __half2* __restrict__ h2 = (const __half2*)g_h;
    float2 acc = make_float2(0.f, 0.f);

    for (int j = s; j < e; j += 32) {
        const int jj = j + lane;
        int   c = 0;
        float v = 0.f;
        if (jj < e) {
            int2 cv = __ldg(&g_csr[jj]);
            c = cv.x;
            v = __int_as_float(cv.y);
        }
        const int cnt = min(32, e - j);
        int i = 0;
        for (; i + 8 <= cnt; i += 8) {
            int   ci[8];
            float vi[8];
            float2 hv[8];
            #pragma unroll
            for (int u = 0; u < 8; u++) {
                ci[u] = __shfl_sync(0xffffffffu, c, i + u);
                vi[u] = __shfl_sync(0xffffffffu, v, i + u);
            }
            #pragma unroll
            for (int u = 0; u < 8; u++)
                hv[u] = __half22float2(__ldg(&h2[(size_t)ci[u] * 32 + lane]));
            #pragma unroll
            for (int u = 0; u < 8; u++) {
                acc.x = fmaf(vi[u], hv[u].x, acc.x);
                acc.y = fmaf(vi[u], hv[u].y, acc.y);
            }
        }
        for (; i < cnt; i++) {
            const int   ci = __shfl_sync(0xffffffffu, c, i);
            const float vi = __shfl_sync(0xffffffffu, v, i);
            const float2 hv = __half22float2(__ldg(&h2[(size_t)ci * 32 + lane]));
            acc.x = fmaf(vi, hv.x, acc.x);
            acc.y = fmaf(vi, hv.y, acc.y);
        }
    }

    acc.x = fmaxf(acc.x, 0.f);
    acc.y = fmaxf(acc.y, 0.f);
    ((float2*)out)[(size_t)gwarp * 32 + lane] = acc;
}

// ---------------- launch: fork-join so CSR build overlaps GEMM ----------------
extern "C" void kernel_launch(void* const* d_in, const int* in_sizes, int n_in,
                              void* d_out, int out_size) {
    const float* X    = (const float*)d_in[0];
    const float* W    = (const float*)d_in[1];
    const float* vals = (const float*)d_in[2];
    const int*   rows = (const int*)d_in[3];
    const int*   cols = (const int*)d_in[4];
    float* out = (float*)d_out;

    static bool init_done = false;
    static cudaStream_t s2;
    static cudaEvent_t ev_fork, ev_join;
    if (!init_done) {
        cudaFuncSetAttribute(k_gemm_tc, cudaFuncAttributeMaxDynamicSharedMemorySize,
                             SMEM_TOTAL);
        cudaStreamCreateWithFlags(&s2, cudaStreamNonBlocking);
        cudaEventCreateWithFlags(&ev_fork, cudaEventDisableTiming);
        cudaEventCreateWithFlags(&ev_join, cudaEventDisableTiming);
        init_done = true;
    }

    // fork: GEMM on the main (capture) stream, CSR chain on s2
    cudaEventRecord(ev_fork, 0);
    cudaStreamWaitEvent(s2, ev_fork, 0);

    k_gemm_tc<<<GGRID, NTHREADS, SMEM_TOTAL>>>(X, W);

    k_zero_deg<<<(N_NODES + 255) / 256, 256, 0, s2>>>();
    k_count<<<(N_EDGES / 2 + 255) / 256, 256, 0, s2>>>(rows);
    k_scan1<<<N_SCAN_BLKS, SCAN_BLK, 0, s2>>>();
    k_scan3<<<N_SCAN_BLKS, SCAN_BLK, 0, s2>>>();
    k_fill<<<(N_EDGES / 2 + 255) / 256, 256, 0, s2>>>(vals, rows, cols);

    // join: spmm needs both branches
    cudaEventRecord(ev_join, s2);
    cudaStreamWaitEvent(0, ev_join, 0);

    k_spmm<<<(N_NODES + 7) / 8, 256>>>(out);
}

// round 16
// speedup vs baseline: 1.0107x; 1.0107x over previous
#include <cuda_runtime.h>
#include <cuda_fp16.h>
#include <cstdint>

#define N_NODES 100000
#define N_EDGES 1600000
#define D_IN    512
#define D_OUT   64

#define SCAN_BLK 1024
#define N_SCAN_BLKS ((N_NODES + SCAN_BLK - 1) / SCAN_BLK)   // 98

#define GGRID   456            // 3 persistent CTAs per SM
#define NTHREADS 256
#define N_UNITS (N_NODES / 16)          // 6250 warp work units (exact)
#define TOTAL_WARPS (GGRID * 8)         // 3648

#define B_SMEM_HALVES (D_IN * D_OUT)    // 32768 halves = 65536 B
#define SMEM_TOTAL (B_SMEM_HALVES * 2)  // 65536 B

// ---------------- scratch -----------------------------------------------------
__device__ __half g_h[N_NODES * D_OUT];      // 12.8 MB fp16
__device__ int   g_deg[N_NODES];
__device__ int   g_rowstart[N_NODES + 1];
__device__ int   g_cursor[N_NODES];
__device__ int   g_bsum[128];
__device__ int2  g_csr[N_EDGES];             // (col, val-as-int)
__device__ int   g_unit_ctr;

// ---------------- helpers -----------------------------------------------------
__device__ __forceinline__ uint32_t smem_u32(const void* p) {
    uint32_t a;
    asm("{ .reg .u64 t; cvta.to.shared.u64 t, %1; cvt.u32.u64 %0, t; }"
        : "=r"(a) : "l"(p));
    return a;
}

__device__ __forceinline__ uint32_t pack_h2(float lo, float hi) {
    __half2 h = __floats2half2_rn(lo, hi);
    return *reinterpret_cast<uint32_t*>(&h);
}

__device__ __forceinline__ void ldsm_x4_t(uint32_t addr, uint32_t r[4]) {
    asm volatile("ldmatrix.sync.aligned.m8n8.x4.trans.shared.b16 {%0,%1,%2,%3}, [%4];"
                 : "=r"(r[0]), "=r"(r[1]), "=r"(r[2]), "=r"(r[3]) : "r"(addr));
}

__device__ __forceinline__ void mma_f16(float c[4], const uint32_t a[4],
                                        uint32_t b0, uint32_t b1) {
    asm volatile(
        "mma.sync.aligned.m16n8k16.row.col.f32.f16.f16.f32 "
        "{%0,%1,%2,%3}, {%4,%5,%6,%7}, {%8,%9}, {%0,%1,%2,%3};"
        : "+f"(c[0]), "+f"(c[1]), "+f"(c[2]), "+f"(c[3])
        : "r"(a[0]), "r"(a[1]), "r"(a[2]), "r"(a[3]), "r"(b0), "r"(b1));
}

// ---------------- GEMM: barrier-free, per-warp queue, depth-2 prefetch --------
__global__ __launch_bounds__(NTHREADS, 3) void k_gemm_tc(const float* __restrict__ X,
                                                         const float* __restrict__ W) {
    extern __shared__ __align__(16) __half Bsm[];  // [512] rows x 128B, XOR-swizzled

    const int tid  = threadIdx.x;
    const int warp = tid >> 5;
    const int lane = tid & 31;
    const int grp  = lane >> 2;
    const int tig  = lane & 3;

    const uint32_t b_base = smem_u32(Bsm);

    // ---- W -> smem fp16, rows k-permuted (perm-inverse), XOR-16B swizzled ----
    for (int i = tid * 8; i < D_IN * D_OUT; i += NTHREADS * 8) {
        const int kk = i >> 6, nn = i & 63;
        const int kl = kk & 15, kh = kk & ~15;
        const int q = kl >> 2, r = kl & 3;
        const int s = (r < 2) ? (2 * q + r) : (8 + 2 * q + (r - 2));
        const int row = kh | s;
        float4 v0 = *(const float4*)&W[i];
        float4 v1 = *(const float4*)&W[i + 4];
        const int u = (nn >> 3) ^ (row & 7);
        *(uint4*)(Bsm + row * 64 + u * 8) =
            make_uint4(pack_h2(v0.x, v0.y), pack_h2(v0.z, v0.w),
                       pack_h2(v1.x, v1.y), pack_h2(v1.z, v1.w));
    }
    __syncthreads();

    const int l15 = lane & 15;
    const int lhi16 = lane >> 4;

    int unit = blockIdx.x * 8 + warp;

    while (unit < N_UNITS) {
        const int r0 = unit * 16 + grp;
        const int r1 = r0 + 8;
        const float* pA0 = X + (size_t)r0 * D_IN + 4 * tig;
        const float* pA1 = X + (size_t)r1 * D_IN + 4 * tig;

        float acc[8][4];
        #pragma unroll
        for (int j = 0; j < 8; j++)
            #pragma unroll
            for (int e = 0; e < 4; e++) acc[j][e] = 0.f;

        float4 v[2][2];
        v[0][0] = *(const float4*)(pA0);
        v[0][1] = *(const float4*)(pA1);
        v[1][0] = *(const float4*)(pA0 + 16);
        v[1][1] = *(const float4*)(pA1 + 16);

        #pragma unroll 4
        for (int kk = 0; kk < 32; kk++) {
            const int sl = kk & 1;
            uint32_t a[4];
            a[0] = pack_h2(v[sl][0].x, v[sl][0].y);
            a[1] = pack_h2(v[sl][1].x, v[sl][1].y);
            a[2] = pack_h2(v[sl][0].z, v[sl][0].w);
            a[3] = pack_h2(v[sl][1].z, v[sl][1].w);

            if (kk + 2 < 32) {   // refill this slot with k-step kk+2
                v[sl][0] = *(const float4*)(pA0 + (kk + 2) * 16);
                v[sl][1] = *(const float4*)(pA1 + (kk + 2) * 16);
            }

            const int brow = kk * 16 + l15;
            const uint32_t brbase = b_base + brow * 128;
            const int bsw = brow & 7;
            uint32_t b[8][2];
            #pragma unroll
            for (int jj = 0; jj < 4; jj++) {
                uint32_t br[4];
                const int u = ((jj << 1) | lhi16) ^ bsw;
                ldsm_x4_t(brbase + (u << 4), br);
                b[2*jj][0]   = br[0];  b[2*jj][1]   = br[1];
                b[2*jj+1][0] = br[2];  b[2*jj+1][1] = br[3];
            }
            #pragma unroll
            for (int j = 0; j < 8; j++)
                mma_f16(acc[j], a, b[j][0], b[j][1]);
        }

        int nxt = 0;
        if (lane == 0) nxt = atomicAdd(&g_unit_ctr, 1);

        #pragma unroll
        for (int j = 0; j < 8; j++) {
            const int col = j * 8 + tig * 2;
            *(uint32_t*)&g_h[(size_t)r0 * D_OUT + col] = pack_h2(acc[j][0], acc[j][1]);
            *(uint32_t*)&g_h[(size_t)r1 * D_OUT + col] = pack_h2(acc[j][2], acc[j][3]);
        }

        unit = __shfl_sync(0xffffffffu, nxt, 0);
    }
}

// ---------------- CSR build ---------------------------------------------------
__global__ void k_zero_deg() {
    int i = blockIdx.x * blockDim.x + threadIdx.x;
    if (i < N_NODES) g_deg[i] = 0;
    if (i == 0) g_unit_ctr = TOTAL_WARPS;
}

__global__ void k_count(const int* __restrict__ rows) {
    int e = (blockIdx.x * blockDim.x + threadIdx.x) * 2;
    if (e + 1 < N_EDGES) {
        int2 r2 = *(const int2*)&rows[e];
        atomicAdd(&g_deg[r2.x], 1);
        atomicAdd(&g_deg[r2.y], 1);
    } else if (e < N_EDGES) {
        atomicAdd(&g_deg[rows[e]], 1);
    }
}

__global__ void k_scan1() {
    __shared__ int wsum[32];
    const int i = blockIdx.x * SCAN_BLK + threadIdx.x;
    const int v = (i < N_NODES) ? g_deg[i] : 0;
    const int lane = threadIdx.x & 31;
    const int w = threadIdx.x >> 5;

    int x = v;
    #pragma unroll
    for (int o = 1; o < 32; o <<= 1) {
        int y = __shfl_up_sync(0xffffffffu, x, o);
        if (lane >= o) x += y;
    }
    if (lane == 31) wsum[w] = x;
    __syncthreads();
    if (w == 0) {
        int s = wsum[lane];
        int t = s;
        #pragma unroll
        for (int o = 1; o < 32; o <<= 1) {
            int y = __shfl_up_sync(0xffffffffu, t, o);
            if (lane >= o) t += y;
        }
        wsum[lane] = t - s;
        if (lane == 31) g_bsum[blockIdx.x] = t;
    }
    __syncthreads();
    const int excl = x - v + wsum[w];
    if (i < N_NODES) g_rowstart[i] = excl;
}

__global__ void k_scan3() {
    __shared__ int s_boff[128];
    __shared__ int wsum[4];
    const int tid = threadIdx.x;
    if (tid < 128) {
        const int lane = tid & 31;
        const int w = tid >> 5;
        const int v = (tid < N_SCAN_BLKS) ? g_bsum[tid] : 0;
        int x = v;
        #pragma unroll
        for (int o = 1; o < 32; o <<= 1) {
            int y = __shfl_up_sync(0xffffffffu, x, o);
            if (lane >= o) x += y;
        }
        if (lane == 31) wsum[w] = x;
    }
    __syncthreads();
    if (tid < 128) {
        const int lane = tid & 31;
        const int w = tid >> 5;
        const int v = (tid < N_SCAN_BLKS) ? g_bsum[tid] : 0;
        int x = v;
        #pragma unroll
        for (int o = 1; o < 32; o <<= 1) {
            int y = __shfl_up_sync(0xffffffffu, x, o);
            if (lane >= o) x += y;
        }
        int woff = 0;
        for (int j = 0; j < w; j++) woff += wsum[j];
        s_boff[tid] = x - v + woff;
    }
    __syncthreads();

    const int i = blockIdx.x * SCAN_BLK + tid;
    if (i < N_NODES) {
        const int val = g_rowstart[i] + s_boff[blockIdx.x];
        g_rowstart[i] = val;
        g_cursor[i] = val;
    }
    if (i == 0) g_rowstart[N_NODES] = N_EDGES;
}

__global__ void k_fill(const float* __restrict__ vals,
                       const int* __restrict__ rows,
                       const int* __restrict__ cols) {
    int e = (blockIdx.x * blockDim.x + threadIdx.x) * 2;
    if (e + 1 < N_EDGES) {
        int2   r2 = *(const int2*)&rows[e];
        int2   c2 = *(const int2*)&cols[e];
        float2 v2 = *(const float2*)&vals[e];
        int p0 = atomicAdd(&g_cursor[r2.x], 1);
        int p1 = atomicAdd(&g_cursor[r2.y], 1);
        g_csr[p0] = make_int2(c2.x, __float_as_int(v2.x));
        g_csr[p1] = make_int2(c2.y, __float_as_int(v2.y));
    } else if (e < N_EDGES) {
        int p = atomicAdd(&g_cursor[rows[e]], 1);
        g_csr[p] = make_int2(cols[e], __float_as_int(vals[e]));
    }
}

// ---------------- SpMM + ReLU: warp per row, 8-wide MLP -----------------------
__global__ void k_spmm(float* __restrict__ out) {
    const int gwarp = (blockIdx.x * blockDim.x + threadIdx.x) >> 5;
    const int lane = threadIdx.x & 31;
    if (gwarp >= N_NODES) return;

    const int s = g_rowstart[gwarp];
    const int e = g_rowstart[gwarp + 1];

    const __half2* __restrict__ h2 = (const __half2*)g_h;
    float2 acc = make_float2(0.f, 0.f);

    for (int j = s; j < e; j += 32) {
        const int jj = j + lane;
        int   c = 0;
        float v = 0.f;
        if (jj < e) {
            int2 cv = __ldg(&g_csr[jj]);
            c = cv.x;
            v = __int_as_float(cv.y);
        }
        const int cnt = min(32, e - j);
        int i = 0;
        for (; i + 8 <= cnt; i += 8) {
            int   ci[8];
            float vi[8];
            float2 hv[8];
            #pragma unroll
            for (int u = 0; u < 8; u++) {
                ci[u] = __shfl_sync(0xffffffffu, c, i + u);
                vi[u] = __shfl_sync(0xffffffffu, v, i + u);
            }
            #pragma unroll
            for (int u = 0; u < 8; u++)
                hv[u] = __half22float2(__ldg(&h2[(size_t)ci[u] * 32 + lane]));
            #pragma unroll
            for (int u = 0; u < 8; u++) {
                acc.x = fmaf(vi[u], hv[u].x, acc.x);
                acc.y = fmaf(vi[u], hv[u].y, acc.y);
            }
        }
        for (; i < cnt; i++) {
            const int   ci = __shfl_sync(0xffffffffu, c, i);
            const float vi = __shfl_sync(0xffffffffu, v, i);
            const float2 hv = __half22float2(__ldg(&h2[(size_t)ci * 32 + lane]));
            acc.x = fmaf(vi, hv.x, acc.x);
            acc.y = fmaf(vi, hv.y, acc.y);
        }
    }

    acc.x = fmaxf(acc.x, 0.f);
    acc.y = fmaxf(acc.y, 0.f);
    ((float2*)out)[(size_t)gwarp * 32 + lane] = acc;
}

// ---------------- launch: fork-join so CSR build overlaps GEMM ----------------
extern "C" void kernel_launch(void* const* d_in, const int* in_sizes, int n_in,
                              void* d_out, int out_size) {
    const float* X    = (const float*)d_in[0];
    const float* W    = (const float*)d_in[1];
    const float* vals = (const float*)d_in[2];
    const int*   rows = (const int*)d_in[3];
    const int*   cols = (const int*)d_in[4];
    float* out = (float*)d_out;

    static bool init_done = false;
    static cudaStream_t s2;
    static cudaEvent_t ev_fork, ev_join;
    if (!init_done) {
        cudaFuncSetAttribute(k_gemm_tc, cudaFuncAttributeMaxDynamicSharedMemorySize,
                             SMEM_TOTAL);
        cudaStreamCreateWithFlags(&s2, cudaStreamNonBlocking);
        cudaEventCreateWithFlags(&ev_fork, cudaEventDisableTiming);
        cudaEventCreateWithFlags(&ev_join, cudaEventDisableTiming);
        init_done = true;
    }

    // fork: GEMM on the main (capture) stream, CSR chain on s2
    cudaEventRecord(ev_fork, 0);
    cudaStreamWaitEvent(s2, ev_fork, 0);

    k_gemm_tc<<<GGRID, NTHREADS, SMEM_TOTAL>>>(X, W);

    k_zero_deg<<<(N_NODES + 255) / 256, 256, 0, s2>>>();
    k_count<<<(N_EDGES / 2 + 255) / 256, 256, 0, s2>>>(rows);
    k_scan1<<<N_SCAN_BLKS, SCAN_BLK, 0, s2>>>();
    k_scan3<<<N_SCAN_BLKS, SCAN_BLK, 0, s2>>>();
    k_fill<<<(N_EDGES / 2 + 255) / 256, 256, 0, s2>>>(vals, rows, cols);

    // join: spmm needs both branches
    cudaEventRecord(ev_join, s2);
    cudaStreamWaitEvent(0, ev_join, 0);

    k_spmm<<<(N_NODES + 7) / 8, 256>>>(out);
}